// round 5
// baseline (speedup 1.0000x reference)
#include <cuda_runtime.h>
#include <cuda_bf16.h>
#include <cstdint>

// ---------------------------------------------------------------------------
// GraphAttentionLayer: N=4096, R=4, Fin=256, Fout=64
//   Wh = h@W; Wh1 = Wh@a[:F]; Wh2 = Wh@a[F:]
//   s  = leaky_relu(Wh1_i + Wh2_j, 0.2) * A[r,i,j]   (A<=0 -> masked)
//   e  = softmax over i (axis=1)  -> column-normalized
//   h' = einsum('rij,jf->rif', e, Wh)  -> warp mma.sync bf16x2, 3 chains,
//        A fragments built directly in registers (no smem round-trip)
//   out = [ elu(h_cat) (N x R*F) | e (R x N x N) ]
// ---------------------------------------------------------------------------

namespace {
constexpr int N    = 4096;
constexpr int R    = 4;
constexpr int FIN  = 256;
constexpr int F    = 64;
constexpr int SEGS = 32;
constexpr int SEGLEN = N / SEGS;     // 128
constexpr int TI   = 128;            // i-tile
constexpr int TJ   = 64;             // j chunk
constexpr int NC   = N / TJ;         // 64
constexpr float ALPHA = 0.2f;

// smem layout (bytes): B double buffer (2 splits each) + linv/wh2 double buf
constexpr int B_STRIDE = 144;
constexpr int B_SPLIT  = F * B_STRIDE;        // 9216
constexpr int B_BUF    = 2 * B_SPLIT;         // 18432
constexpr int OFF_B    = 0;                   // 2 buffers
constexpr int OFF_L    = 2 * B_BUF;           // 36864 ; 2 x 256 B
constexpr int OFF_W2   = OFF_L + 512;         // 37376 ; 2 x 256 B
constexpr int SMEM_TOTAL = OFF_W2 + 512;      // 37888
}

// Scratch (static device globals; no runtime allocation)
__device__ __align__(16) float g_Wh[N * F];                 // 1 MB
__device__ __align__(16) __nv_bfloat16 g_WhT[2][F][N];      // 1 MB, transposed splits
__device__ float g_Wh1[N];
__device__ float g_Wh2[N];
__device__ __align__(16) float g_pl[R * SEGS * N];          // 2 MB partials
__device__ __align__(16) float g_linv[R * N];

// ---------------------------------------------------------------------------
// PTX helpers
// ---------------------------------------------------------------------------
__device__ __forceinline__ uint32_t smem_u32(const void* p) {
    return (uint32_t)__cvta_generic_to_shared(p);
}
__device__ __forceinline__ void cp16(uint32_t dst, const void* src) {
    asm volatile("cp.async.cg.shared.global [%0], [%1], 16;" :: "r"(dst), "l"(src));
}
__device__ __forceinline__ void cp_commit() {
    asm volatile("cp.async.commit_group;");
}
template <int NG>
__device__ __forceinline__ void cp_wait() {
    asm volatile("cp.async.wait_group %0;" :: "n"(NG));
}
__device__ __forceinline__ void ldm4(uint32_t& d0, uint32_t& d1, uint32_t& d2,
                                     uint32_t& d3, uint32_t addr) {
    asm volatile("ldmatrix.sync.aligned.m8n8.x4.shared.b16 {%0,%1,%2,%3}, [%4];"
                 : "=r"(d0), "=r"(d1), "=r"(d2), "=r"(d3) : "r"(addr));
}
__device__ __forceinline__ void mma16816(float* c, const uint32_t* a,
                                         uint32_t b0, uint32_t b1) {
    asm volatile(
        "mma.sync.aligned.m16n8k16.row.col.f32.bf16.bf16.f32 "
        "{%0,%1,%2,%3}, {%4,%5,%6,%7}, {%8,%9}, {%0,%1,%2,%3};"
        : "+f"(c[0]), "+f"(c[1]), "+f"(c[2]), "+f"(c[3])
        : "r"(a[0]), "r"(a[1]), "r"(a[2]), "r"(a[3]), "r"(b0), "r"(b1));
}

// ---------------------------------------------------------------------------
// Kernel 1: Wh [N,F], Wh1[N], Wh2[N].  grid = N blocks x 64 threads.
// ---------------------------------------------------------------------------
__global__ __launch_bounds__(64) void k_wh(const float* __restrict__ h,
                                           const float* __restrict__ W,
                                           const float* __restrict__ a) {
    __shared__ float hs[FIN];
    __shared__ float red[4];
    const int i = blockIdx.x;
    const int f = threadIdx.x;

    #pragma unroll
    for (int k = f; k < FIN; k += 64) hs[k] = h[(size_t)i * FIN + k];
    __syncthreads();

    float acc = 0.f;
    #pragma unroll 8
    for (int k = 0; k < FIN; k++) acc = fmaf(hs[k], W[k * F + f], acc);
    g_Wh[(size_t)i * F + f] = acc;

    float v1 = acc * a[f];
    float v2 = acc * a[F + f];
    #pragma unroll
    for (int off = 16; off; off >>= 1) {
        v1 += __shfl_down_sync(0xffffffffu, v1, off);
        v2 += __shfl_down_sync(0xffffffffu, v2, off);
    }
    if ((f & 31) == 0) { red[f >> 5] = v1; red[2 + (f >> 5)] = v2; }
    __syncthreads();
    if (f == 0) {
        g_Wh1[i] = red[0] + red[1];
        g_Wh2[i] = red[2] + red[3];
    }
}

// ---------------------------------------------------------------------------
// Kernel 1b: transpose + bf16x2 split of Wh -> g_WhT[s][f][j].
// ---------------------------------------------------------------------------
__global__ __launch_bounds__(256) void k_split() {
    __shared__ float sT[F][64 + 1];
    const int i0 = blockIdx.x * 64;
    const int t = threadIdx.x;

    for (int idx = t; idx < 64 * F; idx += 256) {
        const int i = idx >> 6;
        const int f = idx & 63;
        sT[f][i] = g_Wh[(size_t)(i0 + i) * F + f];
    }
    __syncthreads();
    for (int idx = t; idx < 64 * F; idx += 256) {
        const int f  = idx >> 6;
        const int ii = idx & 63;
        const float w = sT[f][ii];
        const __nv_bfloat16 b0 = __float2bfloat16(w);
        const __nv_bfloat16 b1 = __float2bfloat16(w - __bfloat162float(b0));
        g_WhT[0][f][i0 + ii] = b0;
        g_WhT[1][f][i0 + ii] = b1;
    }
}

// ---------------------------------------------------------------------------
// Kernel 2a: partial column sum-exp, float4 per thread.
// grid = (N/1024, SEGS, R) = (4, 32, 4) = 512 blocks, 256 threads.
// ---------------------------------------------------------------------------
__global__ __launch_bounds__(256) void k_stats_part(const float* __restrict__ edge) {
    __shared__ float swh1[SEGLEN];
    const int t   = threadIdx.x;
    const int j   = blockIdx.x * 1024 + 4 * t;
    const int seg = blockIdx.y;
    const int r   = blockIdx.z;
    const int i0  = seg * SEGLEN;

    if (t < SEGLEN) swh1[t] = g_Wh1[i0 + t];
    __syncthreads();

    const float4 w2 = *(const float4*)(g_Wh2 + j);
    const float* base = edge + (size_t)r * N * N + (size_t)i0 * N + j;

    float lx = 0.f, ly = 0.f, lz = 0.f, lw = 0.f;
    #pragma unroll 4
    for (int k = 0; k < SEGLEN; k++) {
        const float4 a = __ldg((const float4*)(base + (size_t)k * N));
        const float xr = swh1[k];
        float x, lr;
        x = xr + w2.x; lr = fmaxf(x, ALPHA * x);
        lx += (a.x > 0.f) ? __expf(lr * a.x) : 0.f;
        x = xr + w2.y; lr = fmaxf(x, ALPHA * x);
        ly += (a.y > 0.f) ? __expf(lr * a.y) : 0.f;
        x = xr + w2.z; lr = fmaxf(x, ALPHA * x);
        lz += (a.z > 0.f) ? __expf(lr * a.z) : 0.f;
        x = xr + w2.w; lr = fmaxf(x, ALPHA * x);
        lw += (a.w > 0.f) ? __expf(lr * a.w) : 0.f;
    }
    float4 out;
    out.x = lx; out.y = ly; out.z = lz; out.w = lw;
    *(float4*)(g_pl + ((size_t)r * SEGS + seg) * N + j) = out;
}

// ---------------------------------------------------------------------------
// Kernel 2b: merge -> g_linv.  grid = R*N/1024 = 16 blocks x 256 threads.
// ---------------------------------------------------------------------------
__global__ __launch_bounds__(256) void k_stats_final() {
    const int idx = blockIdx.x * 256 + threadIdx.x;   // 0..4095
    const int r = idx >> 10;
    const int j = (idx & 1023) * 4;

    float lx = 0.f, ly = 0.f, lz = 0.f, lw = 0.f;
    #pragma unroll
    for (int s = 0; s < SEGS; s++) {
        const float4 p = *(const float4*)(g_pl + ((size_t)r * SEGS + s) * N + j);
        lx += p.x; ly += p.y; lz += p.z; lw += p.w;
    }
    float4 inv;
    inv.x = 1.f / lx; inv.y = 1.f / ly; inv.z = 1.f / lz; inv.w = 1.f / lw;
    *(float4*)(g_linv + (size_t)r * N + j) = inv;
}

// ---------------------------------------------------------------------------
// Kernel 3 (fused): warp w owns rows i0+16w..i0+16w+15; per 64-col chunk:
//   edge LDG directly in MMA-fragment layout (regs, 1-chunk lookahead);
//   transform -> e (gmem) + bf16x2 A fragments in registers;
//   B (WhT splits) + linv/wh2 via cp.async double buffer; 1 sync/chunk;
//   warp mma m16n8k16 bf16, 3 chains, C in registers; elu epilogue.
// grid = (N/TI, R) = 128 blocks, 256 threads.
// ---------------------------------------------------------------------------
__global__ __launch_bounds__(256) void k_fused(const float* __restrict__ edge,
                                               float* __restrict__ out1,
                                               float* __restrict__ outE) {
    extern __shared__ __align__(128) char smc[];
    const uint32_t smb = smem_u32(smc);

    const int t    = threadIdx.x;
    const int wid  = t >> 5;
    const int lane = t & 31;
    const int q    = lane >> 2;       // 0..7 row group
    const int s4   = lane & 3;        // 0..3 col group
    const int r    = blockIdx.y;
    const int i0   = blockIdx.x * TI;
    const size_t ebase = (size_t)r * N * N;
    const bool writeE = (outE != nullptr);

    const int rlo = i0 + 16 * wid + q;
    const int rhi = rlo + 8;
    const float wh1lo = __ldg(g_Wh1 + rlo);
    const float wh1hi = __ldg(g_Wh1 + rhi);

    // ldmatrix B lane base (constant over chunks)
    const uint32_t bLBase = smb + OFF_B +
        (uint32_t)(((lane & 7) + 8 * (lane >> 4)) * B_STRIDE +
                   ((lane >> 3) & 1) * 16);

    auto issue_cpB = [&](int jc) {
        const int buf = jc & 1;
        const int j0 = jc * TJ;
        const uint32_t bBase = smb + OFF_B + buf * B_BUF;
        #pragma unroll
        for (int g = 0; g < 4; g++) {
            const int idx = g * 256 + t;        // 0..1023
            const int s   = idx >> 9;           // split
            const int rem = idx & 511;
            const int row = rem >> 3;           // f row
            const int c16 = rem & 7;
            cp16(bBase + s * B_SPLIT + (uint32_t)(row * B_STRIDE + c16 * 16),
                 &g_WhT[s][row][j0 + c16 * 8]);
        }
        if (t < 16)
            cp16(smb + OFF_L + buf * 256 + t * 16, &g_linv[r * N + j0 + t * 4]);
        else if (t >= 32 && t < 48)
            cp16(smb + OFF_W2 + buf * 256 + (t - 32) * 16, &g_Wh2[j0 + (t - 32) * 4]);
        cp_commit();
    };

    // raw edge in fragment layout: per ks, elements for a0,a1,a2,a3
    auto issue_raw = [&](int jc, float2 (&raw)[16]) {
        #pragma unroll
        for (int ks = 0; ks < 4; ks++) {
            const float* p = edge + ebase + (size_t)rlo * N + jc * TJ + 16 * ks + 2 * s4;
            raw[4 * ks + 0] = __ldg((const float2*)p);
            raw[4 * ks + 1] = __ldg((const float2*)(p + (size_t)8 * N));
            raw[4 * ks + 2] = __ldg((const float2*)(p + 8));
            raw[4 * ks + 3] = __ldg((const float2*)(p + (size_t)8 * N + 8));
        }
    };

    float c[8][4];
    #pragma unroll
    for (int ng = 0; ng < 8; ng++)
        #pragma unroll
        for (int u = 0; u < 4; u++) c[ng][u] = 0.f;

    auto fe = [](float2 av, float wh1, float2 w2, float2 lv) -> float2 {
        float2 e;
        float x = wh1 + w2.x, lr = fmaxf(x, ALPHA * x);
        e.x = (av.x > 0.f) ? __expf(lr * av.x) * lv.x : 0.f;
        x = wh1 + w2.y; lr = fmaxf(x, ALPHA * x);
        e.y = (av.y > 0.f) ? __expf(lr * av.y) * lv.y : 0.f;
        return e;
    };
    auto hx2 = [](float2 v) -> uint32_t {
        const __nv_bfloat162 p = __floats2bfloat162_rn(v.x, v.y);
        return *(const uint32_t*)&p;
    };

    auto step = [&](int jc, float2 (&cur)[16], float2 (&nxt)[16]) {
        cp_wait<0>();
        __syncthreads();    // B(jc)/linv(jc) visible; all warps done with B(jc-1)

        const bool more = (jc + 1 < NC);
        if (more) { issue_cpB(jc + 1); issue_raw(jc + 1, nxt); }

        const int db = jc & 1;
        const int j0 = jc * TJ;
        const float2* sL  = (const float2*)(smc + OFF_L  + db * 256);
        const float2* sW2 = (const float2*)(smc + OFF_W2 + db * 256);
        const uint32_t bBuf = bLBase + db * B_BUF;

        #pragma unroll
        for (int ks = 0; ks < 4; ks++) {
            const int cb = 16 * ks + 2 * s4;              // chunk-local col
            const float2 w2a = sW2[cb >> 1];
            const float2 w2b = sW2[(cb + 8) >> 1];
            const float2 la  = sL[cb >> 1];
            const float2 lb  = sL[(cb + 8) >> 1];

            const float2 e00 = fe(cur[4 * ks + 0], wh1lo, w2a, la);
            const float2 e10 = fe(cur[4 * ks + 1], wh1hi, w2a, la);
            const float2 e01 = fe(cur[4 * ks + 2], wh1lo, w2b, lb);
            const float2 e11 = fe(cur[4 * ks + 3], wh1hi, w2b, lb);

            if (writeE) {
                float* o = outE + ebase + (size_t)rlo * N + j0 + cb;
                *(float2*)o = e00;
                *(float2*)(o + 8) = e01;
                *(float2*)(o + (size_t)8 * N) = e10;
                *(float2*)(o + (size_t)8 * N + 8) = e11;
            }

            // A fragments: hi split + residual split, canonical m16n8k16 layout
            uint32_t aH[4], aL[4];
            aH[0] = hx2(e00); aH[1] = hx2(e10); aH[2] = hx2(e01); aH[3] = hx2(e11);
            {
                const __nv_bfloat162* h0 = (const __nv_bfloat162*)&aH[0];
                float2 d;
                d.x = e00.x - __bfloat162float(h0->x);
                d.y = e00.y - __bfloat162float(h0->y);
                aL[0] = hx2(d);
                const __nv_bfloat162* h1 = (const __nv_bfloat162*)&aH[1];
                d.x = e10.x - __bfloat162float(h1->x);
                d.y = e10.y - __bfloat162float(h1->y);
                aL[1] = hx2(d);
                const __nv_bfloat162* h2 = (const __nv_bfloat162*)&aH[2];
                d.x = e01.x - __bfloat162float(h2->x);
                d.y = e01.y - __bfloat162float(h2->y);
                aL[2] = hx2(d);
                const __nv_bfloat162* h3 = (const __nv_bfloat162*)&aH[3];
                d.x = e11.x - __bfloat162float(h3->x);
                d.y = e11.y - __bfloat162float(h3->y);
                aL[3] = hx2(d);
            }

            #pragma unroll
            for (int ng2 = 0; ng2 < 4; ng2++) {
                const uint32_t bo = bBuf + (uint32_t)(ng2 * 16 * B_STRIDE + ks * 32);
                uint32_t b00, b01, b02, b03, b10, b11, b12, b13;
                ldm4(b00, b01, b02, b03, bo);
                ldm4(b10, b11, b12, b13, bo + B_SPLIT);
                mma16816(c[2 * ng2], aH, b00, b01);
                mma16816(c[2 * ng2], aH, b10, b11);
                mma16816(c[2 * ng2], aL, b00, b01);
                mma16816(c[2 * ng2 + 1], aH, b02, b03);
                mma16816(c[2 * ng2 + 1], aH, b12, b13);
                mma16816(c[2 * ng2 + 1], aL, b02, b03);
            }
        }
    };

    // ---- pipeline ----
    float2 rawP[16], rawQ[16];
    issue_cpB(0);
    issue_raw(0, rawP);
    for (int jc = 0; jc < NC; jc += 2) {
        step(jc, rawP, rawQ);
        step(jc + 1, rawQ, rawP);
    }

    // ---- epilogue: elu + store out1[i, r*F + f] ----
    if (out1 != nullptr) {
        #pragma unroll
        for (int ng = 0; ng < 8; ng++) {
            const int f0 = 8 * ng + 2 * s4;
            float2 v;
            v.x = (c[ng][0] > 0.f) ? c[ng][0] : expm1f(c[ng][0]);
            v.y = (c[ng][1] > 0.f) ? c[ng][1] : expm1f(c[ng][1]);
            *(float2*)(out1 + (size_t)rlo * (R * F) + r * F + f0) = v;
            v.x = (c[ng][2] > 0.f) ? c[ng][2] : expm1f(c[ng][2]);
            v.y = (c[ng][3] > 0.f) ? c[ng][3] : expm1f(c[ng][3]);
            *(float2*)(out1 + (size_t)rhi * (R * F) + r * F + f0) = v;
        }
    }
}

// ---------------------------------------------------------------------------
extern "C" void kernel_launch(void* const* d_in, const int* in_sizes, int n_in,
                              void* d_out, int out_size) {
    const float* h    = (const float*)d_in[0];
    const float* edge = (const float*)d_in[1];
    const float* W    = (const float*)d_in[2];
    const float* a    = (const float*)d_in[3];
    float* out = (float*)d_out;

    const long long size1 = (long long)N * R * F;   // 1,048,576
    const long long sizeE = (long long)R * N * N;   // 67,108,864

    float* out1 = nullptr;
    float* outE = nullptr;
    if ((long long)out_size >= size1 + sizeE) {
        out1 = out;
        outE = out + size1;
    } else if ((long long)out_size >= sizeE) {
        outE = out;
    } else {
        out1 = out;
    }

    cudaFuncSetAttribute(k_fused, cudaFuncAttributeMaxDynamicSharedMemorySize,
                         SMEM_TOTAL);

    k_wh<<<N, 64>>>(h, W, a);
    k_split<<<N / 64, 256>>>();

    dim3 g2(N / 1024, SEGS, R);
    k_stats_part<<<g2, 256>>>(edge);
    k_stats_final<<<(R * N) / 1024, 256>>>();

    dim3 g3(N / TI, R);
    k_fused<<<g3, 256, SMEM_TOTAL>>>(edge, out1, outE);
}

// round 6
// speedup vs baseline: 1.0491x; 1.0491x over previous
#include <cuda_runtime.h>
#include <cuda_bf16.h>
#include <cstdint>

// ---------------------------------------------------------------------------
// GraphAttentionLayer: N=4096, R=4, Fin=256, Fout=64
//   Wh = h@W; Wh1 = Wh@a[:F]; Wh2 = Wh@a[F:]
//   s  = leaky_relu(Wh1_i + Wh2_j, 0.2) * A[r,i,j]   (A<=0 -> masked)
//   e  = softmax over i (axis=1)  -> column-normalized
//   h' = einsum('rij,jf->rif', e, Wh)  -> warp mma.sync bf16x2, 3 chains
//   out = [ elu(h_cat) (N x R*F) | e (R x N x N) ]
//
// R6: j-range split 4x across blocks (512 blocks) with partial-C scratch +
// tiny reduce kernel, for 2x warps/SM and full SM coverage.
// ---------------------------------------------------------------------------

namespace {
constexpr int N    = 4096;
constexpr int R    = 4;
constexpr int FIN  = 256;
constexpr int F    = 64;
constexpr int SEGS = 8;
constexpr int SEGLEN = N / SEGS;     // 512
constexpr int TI   = 128;            // i-tile
constexpr int TJ   = 64;             // j chunk
constexpr int NC   = N / TJ;         // 64
constexpr int JQ   = 4;              // j-split factor
constexpr int CPB  = NC / JQ;        // 16 chunks per block
constexpr float ALPHA = 0.2f;

// smem layout (bytes)
constexpr int B_STRIDE = 144;
constexpr int B_SPLIT  = F * B_STRIDE;        // 9216
constexpr int B_BUF    = 2 * B_SPLIT;         // 18432
constexpr int OFF_B    = 0;                   // 2 buffers
constexpr int OFF_L    = 2 * B_BUF;           // 36864 ; 2 x 256 B
constexpr int OFF_W2   = OFF_L + 512;         // 37376 ; 2 x 256 B
constexpr int OFF_WH1  = OFF_W2 + 512;        // 37888
constexpr int SMEM_TOTAL = OFF_WH1 + TI * 4;  // 38400
}

// Scratch (static device globals; no runtime allocation)
__device__ __align__(16) float g_Wh[N * F];                 // 1 MB
__device__ __align__(16) __nv_bfloat16 g_WhT[2][F][N];      // 1 MB
__device__ float g_Wh1[N];
__device__ float g_Wh2[N];
__device__ float g_pl[R * SEGS * N];
__device__ float g_linv[R * N];
__device__ __align__(16) float g_hp[JQ * R * N * F];        // 16 MB partial h'

// ---------------------------------------------------------------------------
// PTX helpers
// ---------------------------------------------------------------------------
__device__ __forceinline__ uint32_t smem_u32(const void* p) {
    return (uint32_t)__cvta_generic_to_shared(p);
}
__device__ __forceinline__ void cp16(uint32_t dst, const void* src) {
    asm volatile("cp.async.cg.shared.global [%0], [%1], 16;" :: "r"(dst), "l"(src));
}
__device__ __forceinline__ void cp_commit() {
    asm volatile("cp.async.commit_group;");
}
template <int NG>
__device__ __forceinline__ void cp_wait() {
    asm volatile("cp.async.wait_group %0;" :: "n"(NG));
}
__device__ __forceinline__ void ldm4(uint32_t& d0, uint32_t& d1, uint32_t& d2,
                                     uint32_t& d3, uint32_t addr) {
    asm volatile("ldmatrix.sync.aligned.m8n8.x4.shared.b16 {%0,%1,%2,%3}, [%4];"
                 : "=r"(d0), "=r"(d1), "=r"(d2), "=r"(d3) : "r"(addr));
}
__device__ __forceinline__ void mma16816(float* c, const uint32_t* a,
                                         uint32_t b0, uint32_t b1) {
    asm volatile(
        "mma.sync.aligned.m16n8k16.row.col.f32.bf16.bf16.f32 "
        "{%0,%1,%2,%3}, {%4,%5,%6,%7}, {%8,%9}, {%0,%1,%2,%3};"
        : "+f"(c[0]), "+f"(c[1]), "+f"(c[2]), "+f"(c[3])
        : "r"(a[0]), "r"(a[1]), "r"(a[2]), "r"(a[3]), "r"(b0), "r"(b1));
}

// ---------------------------------------------------------------------------
// Kernel 1: Wh [N,F], Wh1[N], Wh2[N].  grid = N blocks x 64 threads.
// ---------------------------------------------------------------------------
__global__ __launch_bounds__(64) void k_wh(const float* __restrict__ h,
                                           const float* __restrict__ W,
                                           const float* __restrict__ a) {
    __shared__ float hs[FIN];
    __shared__ float red[4];
    const int i = blockIdx.x;
    const int f = threadIdx.x;

    #pragma unroll
    for (int k = f; k < FIN; k += 64) hs[k] = h[(size_t)i * FIN + k];
    __syncthreads();

    float acc = 0.f;
    #pragma unroll 8
    for (int k = 0; k < FIN; k++) acc = fmaf(hs[k], W[k * F + f], acc);
    g_Wh[(size_t)i * F + f] = acc;

    float v1 = acc * a[f];
    float v2 = acc * a[F + f];
    #pragma unroll
    for (int off = 16; off; off >>= 1) {
        v1 += __shfl_down_sync(0xffffffffu, v1, off);
        v2 += __shfl_down_sync(0xffffffffu, v2, off);
    }
    if ((f & 31) == 0) { red[f >> 5] = v1; red[2 + (f >> 5)] = v2; }
    __syncthreads();
    if (f == 0) {
        g_Wh1[i] = red[0] + red[1];
        g_Wh2[i] = red[2] + red[3];
    }
}

// ---------------------------------------------------------------------------
// Kernel 1b: transpose + bf16x2 split of Wh -> g_WhT[s][f][j].
// ---------------------------------------------------------------------------
__global__ __launch_bounds__(256) void k_split() {
    __shared__ float sT[F][64 + 1];
    const int i0 = blockIdx.x * 64;
    const int t = threadIdx.x;

    for (int idx = t; idx < 64 * F; idx += 256) {
        const int i = idx >> 6;
        const int f = idx & 63;
        sT[f][i] = g_Wh[(size_t)(i0 + i) * F + f];
    }
    __syncthreads();
    for (int idx = t; idx < 64 * F; idx += 256) {
        const int f  = idx >> 6;
        const int ii = idx & 63;
        const float w = sT[f][ii];
        const __nv_bfloat16 b0 = __float2bfloat16(w);
        const __nv_bfloat16 b1 = __float2bfloat16(w - __bfloat162float(b0));
        g_WhT[0][f][i0 + ii] = b0;
        g_WhT[1][f][i0 + ii] = b1;
    }
}

// ---------------------------------------------------------------------------
// Kernel 2a: partial column sum-exp.  grid = (N/256, SEGS, R), block 256.
// ---------------------------------------------------------------------------
__global__ __launch_bounds__(256) void k_stats_part(const float* __restrict__ edge) {
    __shared__ float swh1[SEGLEN];
    const int j   = blockIdx.x * 256 + threadIdx.x;
    const int seg = blockIdx.y;
    const int r   = blockIdx.z;
    const int i0  = seg * SEGLEN;

    for (int k = threadIdx.x; k < SEGLEN; k += 256) swh1[k] = g_Wh1[i0 + k];
    __syncthreads();

    const float wh2 = g_Wh2[j];
    const float* col = edge + (size_t)r * N * N + (size_t)i0 * N + j;

    float l0 = 0.f, l1 = 0.f, l2 = 0.f, l3 = 0.f;
    #pragma unroll 4
    for (int k = 0; k < SEGLEN; k += 4) {
        const float a0 = __ldg(col + (size_t)k * N);
        const float a1 = __ldg(col + (size_t)(k + 1) * N);
        const float a2 = __ldg(col + (size_t)(k + 2) * N);
        const float a3 = __ldg(col + (size_t)(k + 3) * N);
        const float x0 = swh1[k] + wh2,     x1 = swh1[k + 1] + wh2;
        const float x2 = swh1[k + 2] + wh2, x3 = swh1[k + 3] + wh2;
        const float r0 = fmaxf(x0, ALPHA * x0), r1 = fmaxf(x1, ALPHA * x1);
        const float r2 = fmaxf(x2, ALPHA * x2), r3 = fmaxf(x3, ALPHA * x3);
        l0 += (a0 > 0.f) ? __expf(r0 * a0) : 0.f;
        l1 += (a1 > 0.f) ? __expf(r1 * a1) : 0.f;
        l2 += (a2 > 0.f) ? __expf(r2 * a2) : 0.f;
        l3 += (a3 > 0.f) ? __expf(r3 * a3) : 0.f;
    }
    g_pl[((size_t)r * SEGS + seg) * N + j] = (l0 + l1) + (l2 + l3);
}

__global__ __launch_bounds__(256) void k_stats_final() {
    const int idx = blockIdx.x * 256 + threadIdx.x;
    const int r = idx >> 12;
    const int j = idx & (N - 1);
    float L = 0.f;
    #pragma unroll
    for (int s = 0; s < SEGS; s++) L += g_pl[((size_t)r * SEGS + s) * N + j];
    g_linv[idx] = 1.f / L;
}

// ---------------------------------------------------------------------------
// Kernel 3 (fused): R4 inner loop, j-split 4x across blockIdx.y.
// grid = (N/TI, JQ, R) = (32, 4, 4) = 512 blocks, 256 threads.
// Partial C -> g_hp[jq][r][i][f].
// ---------------------------------------------------------------------------
__global__ __launch_bounds__(256, 2) void k_fused(const float* __restrict__ edge,
                                                  float* __restrict__ outE) {
    extern __shared__ __align__(128) char smc[];
    const uint32_t smb = smem_u32(smc);
    float* sWh1 = (float*)(smc + OFF_WH1);

    const int t    = threadIdx.x;
    const int wid  = t >> 5;
    const int lane = t & 31;
    const int jq   = blockIdx.y;
    const int r    = blockIdx.z;
    const int i0   = blockIdx.x * TI;
    const int jc0  = jq * CPB;
    const size_t ebase = (size_t)r * N * N;
    const bool writeE = (outE != nullptr);

    if (t < TI) sWh1[t] = g_Wh1[i0 + t];
    __syncthreads();

    float wh1v[16];
    #pragma unroll
    for (int k = 0; k < 16; k++) wh1v[k] = sWh1[wid + 8 * k];

    // ldmatrix lane address bases (constant over chunks)
    const uint32_t aLBase = smb + OFF_B;   // unused marker (A stays in old layout)
    (void)aLBase;
    const uint32_t bLBase = smb + OFF_B +
        (uint32_t)(((lane & 7) + 8 * (lane >> 4)) * B_STRIDE +
                   ((lane >> 3) & 1) * 16);

    // A tile staged in smem like R4: reuse the Wh1 region? No: R4 kept A in a
    // dedicated region. Here we re-create it after B (fits: OFF_WH1+512 ... )
    // Instead A smem lives in registers->smem as in R4: allocate after WH1.
    // A region: 2 splits x TI x A_STRIDE bytes.
    constexpr int A_STRIDE = 144;
    constexpr int A_SPLIT  = TI * A_STRIDE;        // 18432
    const uint32_t aBase = smb + OFF_WH1 + 512;    // A region start
    const uint32_t aLd = aBase +
        (uint32_t)((16 * wid + (lane & 7) + 8 * ((lane >> 3) & 1)) * A_STRIDE +
                   (lane >> 4) * 16);

    auto issue_cpB = [&](int jc) {
        const int buf = jc & 1;
        const int j0 = jc * TJ;
        const uint32_t bBase = smb + OFF_B + buf * B_BUF;
        #pragma unroll
        for (int g = 0; g < 4; g++) {
            const int idx = g * 256 + t;        // 0..1023
            const int s   = idx >> 9;           // split
            const int rem = idx & 511;
            const int row = rem >> 3;           // f row
            const int c16 = rem & 7;
            cp16(bBase + s * B_SPLIT + (uint32_t)(row * B_STRIDE + c16 * 16),
                 &g_WhT[s][row][j0 + c16 * 8]);
        }
        if (t < 16)
            cp16(smb + OFF_L + buf * 256 + t * 16, &g_linv[r * N + j0 + t * 4]);
        else if (t >= 32 && t < 48)
            cp16(smb + OFF_W2 + buf * 256 + (t - 32) * 16, &g_Wh2[j0 + (t - 32) * 4]);
        cp_commit();
    };
    auto issue_raw = [&](int jc, float2 (&raw)[16]) {
        const int j0 = jc * TJ;
        const float* base = edge + ebase + (size_t)i0 * N + j0 + 2 * lane;
        #pragma unroll
        for (int k = 0; k < 16; k++)
            raw[k] = __ldg((const float2*)(base + (size_t)(wid + 8 * k) * N));
    };

    float c[8][4];
    #pragma unroll
    for (int ng = 0; ng < 8; ng++)
        #pragma unroll
        for (int u = 0; u < 4; u++) c[ng][u] = 0.f;

    auto step = [&](int jc, float2 (&cur)[16], float2 (&nxt)[16],
                    float2& lnvC, float2& lnvN, float2& w2C, float2& w2N) {
        const int j0 = jc * TJ;
        const bool more = (jc + 1 < jc0 + CPB);
        if (more) {
            issue_cpB(jc + 1);
            issue_raw(jc + 1, nxt);
            lnvN = __ldg((const float2*)(g_linv + r * N + j0 + TJ + 2 * lane));
            w2N  = __ldg((const float2*)(g_Wh2 + j0 + TJ + 2 * lane));
        }

        // ---- transform: raw -> e (gmem) + bf16x2 A splits (smem) ----
        #pragma unroll
        for (int k = 0; k < 16; k++) {
            const int row = wid + 8 * k;
            const float wh1 = wh1v[k];
            const float2 av = cur[k];
            float2 ev;
            {
                const float x = wh1 + w2C.x, lr = fmaxf(x, ALPHA * x);
                ev.x = (av.x > 0.f) ? __expf(lr * av.x) * lnvC.x : 0.f;
            }
            {
                const float x = wh1 + w2C.y, lr = fmaxf(x, ALPHA * x);
                ev.y = (av.y > 0.f) ? __expf(lr * av.y) * lnvC.y : 0.f;
            }
            if (writeE)
                *(float2*)(outE + ebase + (size_t)(i0 + row) * N + j0 + 2 * lane) = ev;

            __nv_bfloat162 p0 = __floats2bfloat162_rn(ev.x, ev.y);
            const float rx = ev.x - __bfloat162float(p0.x);
            const float ry = ev.y - __bfloat162float(p0.y);
            __nv_bfloat162 p1 = __floats2bfloat162_rn(rx, ry);
            const uint32_t so = (uint32_t)(row * A_STRIDE + lane * 4);
            asm volatile("st.shared.b32 [%0], %1;"
                         :: "r"(aBase + so), "r"(*(uint32_t*)&p0));
            asm volatile("st.shared.b32 [%0], %1;"
                         :: "r"(aBase + A_SPLIT + so), "r"(*(uint32_t*)&p1));
        }

        if (more) cp_wait<1>(); else cp_wait<0>();
        __syncthreads();

        // ---- MMA: 4 k-steps x 4 n16-groups x 3 chains ----
        const uint32_t bBuf = bLBase + (jc & 1) * B_BUF;
        #pragma unroll
        for (int ks = 0; ks < 4; ks++) {
            uint32_t a0[4], a1[4];
            ldm4(a0[0], a0[1], a0[2], a0[3], aLd + ks * 32);
            ldm4(a1[0], a1[1], a1[2], a1[3], aLd + A_SPLIT + ks * 32);
            #pragma unroll
            for (int ng2 = 0; ng2 < 4; ng2++) {
                const uint32_t bo = bBuf + (uint32_t)(ng2 * 16 * B_STRIDE + ks * 32);
                uint32_t b00, b01, b02, b03, b10, b11, b12, b13;
                ldm4(b00, b01, b02, b03, bo);
                ldm4(b10, b11, b12, b13, bo + B_SPLIT);
                mma16816(c[2 * ng2], a0, b00, b01);
                mma16816(c[2 * ng2], a0, b10, b11);
                mma16816(c[2 * ng2], a1, b00, b01);
                mma16816(c[2 * ng2 + 1], a0, b02, b03);
                mma16816(c[2 * ng2 + 1], a0, b12, b13);
                mma16816(c[2 * ng2 + 1], a1, b02, b03);
            }
        }
        __syncthreads();

        lnvC = lnvN; w2C = w2N;
    };

    // ---- pipeline ----
    float2 rawP[16], rawQ[16];
    float2 lnvC, lnvN, w2C, w2N;
    issue_cpB(jc0);
    issue_raw(jc0, rawP);
    lnvC = __ldg((const float2*)(g_linv + r * N + jc0 * TJ + 2 * lane));
    w2C  = __ldg((const float2*)(g_Wh2 + jc0 * TJ + 2 * lane));
    lnvN = lnvC; w2N = w2C;

    for (int s = 0; s < CPB; s += 2) {
        step(jc0 + s, rawP, rawQ, lnvC, lnvN, w2C, w2N);
        step(jc0 + s + 1, rawQ, rawP, lnvC, lnvN, w2C, w2N);
    }

    // ---- store partial C -> g_hp[jq][r][i][f] (no elu) ----
    {
        float* hp = g_hp + ((size_t)(jq * R + r) * N) * F;
        const int r0 = i0 + 16 * wid + (lane >> 2);
        #pragma unroll
        for (int ng = 0; ng < 8; ng++) {
            const int f0 = 8 * ng + 2 * (lane & 3);
            *(float2*)(hp + (size_t)r0 * F + f0) = *(float2*)&c[ng][0];
            *(float2*)(hp + (size_t)(r0 + 8) * F + f0) = *(float2*)&c[ng][2];
        }
    }
}

// ---------------------------------------------------------------------------
// Kernel 4: reduce partials + elu -> out1[i, r*F+f].
// grid = N*R*F/(4*256) = 1024 blocks x 256 threads (float4 per thread).
// ---------------------------------------------------------------------------
__global__ __launch_bounds__(256) void k_elu(float* __restrict__ out1) {
    if (out1 == nullptr) return;
    const int v = blockIdx.x * 256 + threadIdx.x;    // float4 index
    const int f0 = (v & 15) * 4;
    const int r  = (v >> 4) & 3;
    const int i  = v >> 6;

    float4 s = make_float4(0.f, 0.f, 0.f, 0.f);
    #pragma unroll
    for (int jq = 0; jq < JQ; jq++) {
        const float4 p = *(const float4*)(
            g_hp + ((size_t)(jq * R + r) * N + i) * F + f0);
        s.x += p.x; s.y += p.y; s.z += p.z; s.w += p.w;
    }
    float4 o;
    o.x = (s.x > 0.f) ? s.x : expm1f(s.x);
    o.y = (s.y > 0.f) ? s.y : expm1f(s.y);
    o.z = (s.z > 0.f) ? s.z : expm1f(s.z);
    o.w = (s.w > 0.f) ? s.w : expm1f(s.w);
    *(float4*)(out1 + (size_t)v * 4) = o;
}

// ---------------------------------------------------------------------------
extern "C" void kernel_launch(void* const* d_in, const int* in_sizes, int n_in,
                              void* d_out, int out_size) {
    const float* h    = (const float*)d_in[0];
    const float* edge = (const float*)d_in[1];
    const float* W    = (const float*)d_in[2];
    const float* a    = (const float*)d_in[3];
    float* out = (float*)d_out;

    const long long size1 = (long long)N * R * F;   // 1,048,576
    const long long sizeE = (long long)R * N * N;   // 67,108,864

    float* out1 = nullptr;
    float* outE = nullptr;
    if ((long long)out_size >= size1 + sizeE) {
        out1 = out;
        outE = out + size1;
    } else if ((long long)out_size >= sizeE) {
        outE = out;
    } else {
        out1 = out;
    }

    // A region (2 x 18432) lives after OFF_WH1+512
    const int smemBytes = OFF_WH1 + 512 + 2 * (TI * 144);   // 75776
    cudaFuncSetAttribute(k_fused, cudaFuncAttributeMaxDynamicSharedMemorySize,
                         smemBytes);

    k_wh<<<N, 64>>>(h, W, a);
    k_split<<<N / 64, 256>>>();

    dim3 g2(N / 256, SEGS, R);
    k_stats_part<<<g2, 256>>>(edge);
    k_stats_final<<<(R * N) / 256, 256>>>();

    dim3 g3(N / TI, JQ, R);
    k_fused<<<g3, 256, smemBytes>>>(edge, outE);

    k_elu<<<(N * R * F) / 1024, 256>>>(out1);
}

// round 7
// speedup vs baseline: 1.3662x; 1.3023x over previous
#include <cuda_runtime.h>
#include <cuda_bf16.h>
#include <cstdint>

// ---------------------------------------------------------------------------
// GraphAttentionLayer: N=4096, R=4, Fin=256, Fout=64
//   Wh = h@W; Wh1 = Wh@a[:F]; Wh2 = Wh@a[F:]
//   s  = leaky_relu(Wh1_i + Wh2_j, 0.2) * A[r,i,j]   (A<=0 -> masked)
//   e  = softmax over i (axis=1)  -> column-normalized
//   h' = einsum('rij,jf->rif', e, Wh)  -> warp mma.sync bf16x2, 3 chains
//   out = [ elu(h_cat) (N x R*F) | e (R x N x N) ]
//
// R7: R4 inner loop, i-tile halved to 64 -> 256 blocks, 2 blocks/SM
// co-resident (4 warps/SMSP), full j-length per block (no drain overhead).
// ---------------------------------------------------------------------------

namespace {
constexpr int N    = 4096;
constexpr int R    = 4;
constexpr int FIN  = 256;
constexpr int F    = 64;
constexpr int SEGS = 8;
constexpr int SEGLEN = N / SEGS;     // 512
constexpr int TI   = 64;             // i-tile
constexpr int TJ   = 64;             // j chunk
constexpr int NC   = N / TJ;         // 64
constexpr float ALPHA = 0.2f;

// smem layout (bytes)
constexpr int B_STRIDE = 144;
constexpr int B_SPLIT  = F * B_STRIDE;        // 9216
constexpr int B_BUF    = 2 * B_SPLIT;         // 18432
constexpr int OFF_B    = 0;                   // 2 buffers
constexpr int OFF_L    = 2 * B_BUF;           // 36864 ; 2 x 256 B
constexpr int OFF_W2   = OFF_L + 512;         // 37376 ; 2 x 256 B
constexpr int OFF_WH1  = OFF_W2 + 512;        // 37888 ; 64 floats
constexpr int A_STRIDE = 144;
constexpr int A_SPLIT  = TI * A_STRIDE;       // 9216
constexpr int OFF_A    = OFF_WH1 + 256;       // 38144 ; 2 splits
constexpr int SMEM_TOTAL = OFF_A + 2 * A_SPLIT;  // 56576
}

// Scratch (static device globals; no runtime allocation)
__device__ __align__(16) float g_Wh[N * F];                 // 1 MB
__device__ __align__(16) __nv_bfloat16 g_WhT[2][F][N];      // 1 MB
__device__ float g_Wh1[N];
__device__ float g_Wh2[N];
__device__ float g_pl[R * SEGS * N];
__device__ float g_linv[R * N];

// ---------------------------------------------------------------------------
// PTX helpers
// ---------------------------------------------------------------------------
__device__ __forceinline__ uint32_t smem_u32(const void* p) {
    return (uint32_t)__cvta_generic_to_shared(p);
}
__device__ __forceinline__ void cp16(uint32_t dst, const void* src) {
    asm volatile("cp.async.cg.shared.global [%0], [%1], 16;" :: "r"(dst), "l"(src));
}
__device__ __forceinline__ void cp_commit() {
    asm volatile("cp.async.commit_group;");
}
template <int NG>
__device__ __forceinline__ void cp_wait() {
    asm volatile("cp.async.wait_group %0;" :: "n"(NG));
}
__device__ __forceinline__ void ldm4(uint32_t& d0, uint32_t& d1, uint32_t& d2,
                                     uint32_t& d3, uint32_t addr) {
    asm volatile("ldmatrix.sync.aligned.m8n8.x4.shared.b16 {%0,%1,%2,%3}, [%4];"
                 : "=r"(d0), "=r"(d1), "=r"(d2), "=r"(d3) : "r"(addr));
}
__device__ __forceinline__ void mma16816(float* c, const uint32_t* a,
                                         uint32_t b0, uint32_t b1) {
    asm volatile(
        "mma.sync.aligned.m16n8k16.row.col.f32.bf16.bf16.f32 "
        "{%0,%1,%2,%3}, {%4,%5,%6,%7}, {%8,%9}, {%0,%1,%2,%3};"
        : "+f"(c[0]), "+f"(c[1]), "+f"(c[2]), "+f"(c[3])
        : "r"(a[0]), "r"(a[1]), "r"(a[2]), "r"(a[3]), "r"(b0), "r"(b1));
}

// ---------------------------------------------------------------------------
// Kernel 1: Wh [N,F], Wh1[N], Wh2[N].  grid = N blocks x 64 threads.
// ---------------------------------------------------------------------------
__global__ __launch_bounds__(64) void k_wh(const float* __restrict__ h,
                                           const float* __restrict__ W,
                                           const float* __restrict__ a) {
    __shared__ float hs[FIN];
    __shared__ float red[4];
    const int i = blockIdx.x;
    const int f = threadIdx.x;

    #pragma unroll
    for (int k = f; k < FIN; k += 64) hs[k] = h[(size_t)i * FIN + k];
    __syncthreads();

    float acc = 0.f;
    #pragma unroll 8
    for (int k = 0; k < FIN; k++) acc = fmaf(hs[k], W[k * F + f], acc);
    g_Wh[(size_t)i * F + f] = acc;

    float v1 = acc * a[f];
    float v2 = acc * a[F + f];
    #pragma unroll
    for (int off = 16; off; off >>= 1) {
        v1 += __shfl_down_sync(0xffffffffu, v1, off);
        v2 += __shfl_down_sync(0xffffffffu, v2, off);
    }
    if ((f & 31) == 0) { red[f >> 5] = v1; red[2 + (f >> 5)] = v2; }
    __syncthreads();
    if (f == 0) {
        g_Wh1[i] = red[0] + red[1];
        g_Wh2[i] = red[2] + red[3];
    }
}

// ---------------------------------------------------------------------------
// Kernel 1b: transpose + bf16x2 split of Wh -> g_WhT[s][f][j].
// ---------------------------------------------------------------------------
__global__ __launch_bounds__(256) void k_split() {
    __shared__ float sT[F][64 + 1];
    const int i0 = blockIdx.x * 64;
    const int t = threadIdx.x;

    for (int idx = t; idx < 64 * F; idx += 256) {
        const int i = idx >> 6;
        const int f = idx & 63;
        sT[f][i] = g_Wh[(size_t)(i0 + i) * F + f];
    }
    __syncthreads();
    for (int idx = t; idx < 64 * F; idx += 256) {
        const int f  = idx >> 6;
        const int ii = idx & 63;
        const float w = sT[f][ii];
        const __nv_bfloat16 b0 = __float2bfloat16(w);
        const __nv_bfloat16 b1 = __float2bfloat16(w - __bfloat162float(b0));
        g_WhT[0][f][i0 + ii] = b0;
        g_WhT[1][f][i0 + ii] = b1;
    }
}

// ---------------------------------------------------------------------------
// Kernel 2a: partial column sum-exp.  grid = (N/256, SEGS, R), block 256.
// ---------------------------------------------------------------------------
__global__ __launch_bounds__(256) void k_stats_part(const float* __restrict__ edge) {
    __shared__ float swh1[SEGLEN];
    const int j   = blockIdx.x * 256 + threadIdx.x;
    const int seg = blockIdx.y;
    const int r   = blockIdx.z;
    const int i0  = seg * SEGLEN;

    for (int k = threadIdx.x; k < SEGLEN; k += 256) swh1[k] = g_Wh1[i0 + k];
    __syncthreads();

    const float wh2 = g_Wh2[j];
    const float* col = edge + (size_t)r * N * N + (size_t)i0 * N + j;

    float l0 = 0.f, l1 = 0.f, l2 = 0.f, l3 = 0.f;
    #pragma unroll 4
    for (int k = 0; k < SEGLEN; k += 4) {
        const float a0 = __ldg(col + (size_t)k * N);
        const float a1 = __ldg(col + (size_t)(k + 1) * N);
        const float a2 = __ldg(col + (size_t)(k + 2) * N);
        const float a3 = __ldg(col + (size_t)(k + 3) * N);
        const float x0 = swh1[k] + wh2,     x1 = swh1[k + 1] + wh2;
        const float x2 = swh1[k + 2] + wh2, x3 = swh1[k + 3] + wh2;
        const float r0 = fmaxf(x0, ALPHA * x0), r1 = fmaxf(x1, ALPHA * x1);
        const float r2 = fmaxf(x2, ALPHA * x2), r3 = fmaxf(x3, ALPHA * x3);
        l0 += (a0 > 0.f) ? __expf(r0 * a0) : 0.f;
        l1 += (a1 > 0.f) ? __expf(r1 * a1) : 0.f;
        l2 += (a2 > 0.f) ? __expf(r2 * a2) : 0.f;
        l3 += (a3 > 0.f) ? __expf(r3 * a3) : 0.f;
    }
    g_pl[((size_t)r * SEGS + seg) * N + j] = (l0 + l1) + (l2 + l3);
}

__global__ __launch_bounds__(256) void k_stats_final() {
    const int idx = blockIdx.x * 256 + threadIdx.x;
    const int r = idx >> 12;
    const int j = idx & (N - 1);
    float L = 0.f;
    #pragma unroll
    for (int s = 0; s < SEGS; s++) L += g_pl[((size_t)r * SEGS + s) * N + j];
    g_linv[idx] = 1.f / L;
}

// ---------------------------------------------------------------------------
// Kernel 3 (fused): per (r, 64-row tile), all 64 j-chunks.
// Warp w: m-group = w>>1 (16 rows), n-half = w&1 (32 of 64 f-cols).
// Each warp transforms 8 rows (its m-group half) and computes m16 x n32 MMA.
// grid = (N/TI, R) = (64, 4) = 256 blocks, 256 threads, 2 blocks/SM.
// ---------------------------------------------------------------------------
__global__ __launch_bounds__(256, 2) void k_fused(const float* __restrict__ edge,
                                                  float* __restrict__ out1,
                                                  float* __restrict__ outE) {
    extern __shared__ __align__(128) char smc[];
    const uint32_t smb = smem_u32(smc);
    float* sWh1 = (float*)(smc + OFF_WH1);

    const int t    = threadIdx.x;
    const int wid  = t >> 5;
    const int lane = t & 31;
    const int mg   = wid >> 1;        // 0..3 m-group (16 rows)
    const int nh   = wid & 1;         // 0..1 n-half (32 cols)
    const int r    = blockIdx.y;
    const int i0   = blockIdx.x * TI;
    const size_t ebase = (size_t)r * N * N;
    const bool writeE = (outE != nullptr);

    if (t < TI) sWh1[t] = g_Wh1[i0 + t];
    __syncthreads();

    const int trow = 16 * mg + 8 * nh;    // transform row base (8 rows)
    float wh1v[8];
    #pragma unroll
    for (int k = 0; k < 8; k++) wh1v[k] = sWh1[trow + k];

    // ldmatrix lane address bases (constant over chunks)
    const uint32_t aBase = smb + OFF_A;
    const uint32_t aLd = aBase +
        (uint32_t)((16 * mg + (lane & 7) + 8 * ((lane >> 3) & 1)) * A_STRIDE +
                   (lane >> 4) * 16);
    const uint32_t bLBase = smb + OFF_B +
        (uint32_t)(((lane & 7) + 8 * (lane >> 4)) * B_STRIDE +
                   ((lane >> 3) & 1) * 16);

    auto issue_cpB = [&](int jc) {
        const int buf = jc & 1;
        const int j0 = jc * TJ;
        const uint32_t bBase = smb + OFF_B + buf * B_BUF;
        #pragma unroll
        for (int g = 0; g < 4; g++) {
            const int idx = g * 256 + t;        // 0..1023
            const int s   = idx >> 9;           // split
            const int rem = idx & 511;
            const int row = rem >> 3;           // f row
            const int c16 = rem & 7;
            cp16(bBase + s * B_SPLIT + (uint32_t)(row * B_STRIDE + c16 * 16),
                 &g_WhT[s][row][j0 + c16 * 8]);
        }
        if (t < 16)
            cp16(smb + OFF_L + buf * 256 + t * 16, &g_linv[r * N + j0 + t * 4]);
        else if (t >= 32 && t < 48)
            cp16(smb + OFF_W2 + buf * 256 + (t - 32) * 16, &g_Wh2[j0 + (t - 32) * 4]);
        cp_commit();
    };
    auto issue_raw = [&](int jc, float2 (&raw)[8]) {
        const int j0 = jc * TJ;
        const float* base = edge + ebase + (size_t)(i0 + trow) * N + j0 + 2 * lane;
        #pragma unroll
        for (int k = 0; k < 8; k++)
            raw[k] = __ldg((const float2*)(base + (size_t)k * N));
    };

    float c[4][4];
    #pragma unroll
    for (int ng = 0; ng < 4; ng++)
        #pragma unroll
        for (int u = 0; u < 4; u++) c[ng][u] = 0.f;

    auto step = [&](int jc, float2 (&cur)[8], float2 (&nxt)[8],
                    float2& lnvC, float2& lnvN, float2& w2C, float2& w2N) {
        const int j0 = jc * TJ;
        const bool more = (jc + 1 < NC);
        if (more) {
            issue_cpB(jc + 1);
            issue_raw(jc + 1, nxt);
            lnvN = __ldg((const float2*)(g_linv + r * N + j0 + TJ + 2 * lane));
            w2N  = __ldg((const float2*)(g_Wh2 + j0 + TJ + 2 * lane));
        }

        // ---- transform: raw -> e (gmem) + bf16x2 A splits (smem) ----
        #pragma unroll
        for (int k = 0; k < 8; k++) {
            const int row = trow + k;
            const float wh1 = wh1v[k];
            const float2 av = cur[k];
            float2 ev;
            {
                const float x = wh1 + w2C.x, lr = fmaxf(x, ALPHA * x);
                ev.x = (av.x > 0.f) ? __expf(lr * av.x) * lnvC.x : 0.f;
            }
            {
                const float x = wh1 + w2C.y, lr = fmaxf(x, ALPHA * x);
                ev.y = (av.y > 0.f) ? __expf(lr * av.y) * lnvC.y : 0.f;
            }
            if (writeE)
                *(float2*)(outE + ebase + (size_t)(i0 + row) * N + j0 + 2 * lane) = ev;

            __nv_bfloat162 p0 = __floats2bfloat162_rn(ev.x, ev.y);
            const float rx = ev.x - __bfloat162float(p0.x);
            const float ry = ev.y - __bfloat162float(p0.y);
            __nv_bfloat162 p1 = __floats2bfloat162_rn(rx, ry);
            const uint32_t so = (uint32_t)(row * A_STRIDE + lane * 4);
            asm volatile("st.shared.b32 [%0], %1;"
                         :: "r"(aBase + so), "r"(*(uint32_t*)&p0));
            asm volatile("st.shared.b32 [%0], %1;"
                         :: "r"(aBase + A_SPLIT + so), "r"(*(uint32_t*)&p1));
        }

        if (more) cp_wait<1>(); else cp_wait<0>();
        __syncthreads();

        // ---- MMA: 4 k-steps x 2 n16-groups (this warp's half) x 3 chains ----
        const uint32_t bBuf = bLBase + (jc & 1) * B_BUF;
        #pragma unroll
        for (int ks = 0; ks < 4; ks++) {
            uint32_t a0[4], a1[4];
            ldm4(a0[0], a0[1], a0[2], a0[3], aLd + ks * 32);
            ldm4(a1[0], a1[1], a1[2], a1[3], aLd + A_SPLIT + ks * 32);
            #pragma unroll
            for (int u = 0; u < 2; u++) {
                const int ng2 = 2 * nh + u;
                const uint32_t bo = bBuf + (uint32_t)(ng2 * 16 * B_STRIDE + ks * 32);
                uint32_t b00, b01, b02, b03, b10, b11, b12, b13;
                ldm4(b00, b01, b02, b03, bo);
                ldm4(b10, b11, b12, b13, bo + B_SPLIT);
                mma16816(c[2 * u], a0, b00, b01);
                mma16816(c[2 * u], a0, b10, b11);
                mma16816(c[2 * u], a1, b00, b01);
                mma16816(c[2 * u + 1], a0, b02, b03);
                mma16816(c[2 * u + 1], a0, b12, b13);
                mma16816(c[2 * u + 1], a1, b02, b03);
            }
        }
        __syncthreads();

        lnvC = lnvN; w2C = w2N;
    };

    // ---- pipeline ----
    float2 rawP[8], rawQ[8];
    float2 lnvC, lnvN, w2C, w2N;
    issue_cpB(0);
    issue_raw(0, rawP);
    lnvC = __ldg((const float2*)(g_linv + r * N + 2 * lane));
    w2C  = __ldg((const float2*)(g_Wh2 + 2 * lane));
    lnvN = lnvC; w2N = w2C;

    for (int jc = 0; jc < NC; jc += 2) {
        step(jc, rawP, rawQ, lnvC, lnvN, w2C, w2N);
        step(jc + 1, rawQ, rawP, lnvC, lnvN, w2C, w2N);
    }

    // ---- epilogue: elu + store out1[i, r*F + f] ----
    if (out1 != nullptr) {
        const int rlo = i0 + 16 * mg + (lane >> 2);
        const int rhi = rlo + 8;
        #pragma unroll
        for (int u = 0; u < 2; u++) {
            const int ng2 = 2 * nh + u;
            #pragma unroll
            for (int v = 0; v < 2; v++) {
                const int f0 = 8 * (2 * ng2 + v) + 2 * (lane & 3);
                const float* cc = c[2 * u + v];
                float2 o;
                o.x = (cc[0] > 0.f) ? cc[0] : expm1f(cc[0]);
                o.y = (cc[1] > 0.f) ? cc[1] : expm1f(cc[1]);
                *(float2*)(out1 + (size_t)rlo * (R * F) + r * F + f0) = o;
                o.x = (cc[2] > 0.f) ? cc[2] : expm1f(cc[2]);
                o.y = (cc[3] > 0.f) ? cc[3] : expm1f(cc[3]);
                *(float2*)(out1 + (size_t)rhi * (R * F) + r * F + f0) = o;
            }
        }
    }
}

// ---------------------------------------------------------------------------
extern "C" void kernel_launch(void* const* d_in, const int* in_sizes, int n_in,
                              void* d_out, int out_size) {
    const float* h    = (const float*)d_in[0];
    const float* edge = (const float*)d_in[1];
    const float* W    = (const float*)d_in[2];
    const float* a    = (const float*)d_in[3];
    float* out = (float*)d_out;

    const long long size1 = (long long)N * R * F;   // 1,048,576
    const long long sizeE = (long long)R * N * N;   // 67,108,864

    float* out1 = nullptr;
    float* outE = nullptr;
    if ((long long)out_size >= size1 + sizeE) {
        out1 = out;
        outE = out + size1;
    } else if ((long long)out_size >= sizeE) {
        outE = out;
    } else {
        out1 = out;
    }

    cudaFuncSetAttribute(k_fused, cudaFuncAttributeMaxDynamicSharedMemorySize,
                         SMEM_TOTAL);

    k_wh<<<N, 64>>>(h, W, a);
    k_split<<<N / 64, 256>>>();

    dim3 g2(N / 256, SEGS, R);
    k_stats_part<<<g2, 256>>>(edge);
    k_stats_final<<<(R * N) / 256, 256>>>();

    dim3 g3(N / TI, R);
    k_fused<<<g3, 256, SMEM_TOTAL>>>(edge, out1, outE);
}